// round 14
// baseline (speedup 1.0000x reference)
#include <cuda_runtime.h>
#include <cuda_bf16.h>
#include <cstdint>
#include <cfloat>

#define B_    64
#define N_    512
#define BN_   32768
#define K_    8
#define H_    336
#define C_    256

// ---------------- scratch (static device memory) ----------------
__device__ int   g_knn[BN_ * K_];
__device__ float g_norm[BN_];
__device__ float g_m[(size_t)BN_ * C_];
__device__ float g_pool[B_ * C_];
__device__ float g_bcomb[672];
__device__ float g_candd[(size_t)BN_ * 32];
__device__ int   g_candi[(size_t)BN_ * 32];
__device__ __nv_bfloat16 g_xsh[BN_ * 64],  g_xsl[BN_ * 64];
__device__ __nv_bfloat16 g_xoh[4 * (size_t)BN_ * C_], g_xol[4 * (size_t)BN_ * C_];
__device__ __nv_bfloat16 g_abh[(size_t)BN_ * 768], g_abl[(size_t)BN_ * 768];
__device__ __nv_bfloat16 g_cath[(size_t)BN_ * 1088], g_catl[(size_t)BN_ * 1088];
__device__ __nv_bfloat16 g_th[(size_t)BN_ * 384], g_tl[(size_t)BN_ * 384];
__device__ __nv_bfloat16 g_bh1[672 * 1088], g_bl1[672 * 1088];
__device__ __nv_bfloat16 g_bh2[256 * 384],  g_bl2[256 * 384];

__device__ __forceinline__ float lrelu(float v) { return v >= 0.f ? v : 0.01f * v; }
__device__ __forceinline__ uint32_t sw64(int row, int b) {
    return (uint32_t)(row * 64 + (b ^ (((row >> 1) & 3) << 4)));
}
__device__ __forceinline__ uint32_t smem_u32(const void* p) {
    uint32_t a;
    asm("{ .reg .u64 t; cvta.to.shared.u64 t, %1; cvt.u32.u64 %0, t; }" : "=r"(a) : "l"(p));
    return a;
}
__device__ __forceinline__ void ldsm4(uint32_t r[4], uint32_t addr) {
    asm volatile("ldmatrix.sync.aligned.m8n8.x4.shared.b16 {%0,%1,%2,%3}, [%4];"
                 : "=r"(r[0]), "=r"(r[1]), "=r"(r[2]), "=r"(r[3]) : "r"(addr));
}
__device__ __forceinline__ void mma_bf16(float c[4], const uint32_t a[4],
                                         uint32_t b0, uint32_t b1) {
    asm volatile(
        "mma.sync.aligned.m16n8k16.row.col.f32.bf16.bf16.f32 "
        "{%0,%1,%2,%3}, {%4,%5,%6,%7}, {%8,%9}, {%0,%1,%2,%3};"
        : "+f"(c[0]), "+f"(c[1]), "+f"(c[2]), "+f"(c[3])
        : "r"(a[0]), "r"(a[1]), "r"(a[2]), "r"(a[3]), "r"(b0), "r"(b1));
}
__device__ __forceinline__ void cpa16(uint32_t dst, const void* src, bool pred) {
    int sz = pred ? 16 : 0;
    asm volatile("cp.async.cg.shared.global [%0], [%1], 16, %2;"
                 :: "r"(dst), "l"(src), "r"(sz));
}
#define CP_COMMIT() asm volatile("cp.async.commit_group;" ::: "memory")
#define CP_WAIT0()  asm volatile("cp.async.wait_group 0;" ::: "memory")
#define CP_WAIT1()  asm volatile("cp.async.wait_group 1;" ::: "memory")

__device__ __forceinline__ void store8(char* sh, char* sl, int row, int colbyte,
                                       const float* v) {
    alignas(16) __nv_bfloat16 h[8];
    alignas(16) __nv_bfloat16 l[8];
#pragma unroll
    for (int q = 0; q < 8; ++q) {
        h[q] = __float2bfloat16(v[q]);
        l[q] = __float2bfloat16(v[q] - __bfloat162float(h[q]));
    }
    uint32_t so = sw64(row, colbyte);
    *reinterpret_cast<uint4*>(sh + so) = *reinterpret_cast<const uint4*>(h);
    *reinterpret_cast<uint4*>(sl + so) = *reinterpret_cast<const uint4*>(l);
}
__device__ __forceinline__ void wpair(__nv_bfloat16* H, __nv_bfloat16* L, size_t off,
                                      float v0, float v1) {
    __nv_bfloat16 h0 = __float2bfloat16(v0), h1 = __float2bfloat16(v1);
    __nv_bfloat16 l0 = __float2bfloat16(v0 - __bfloat162float(h0));
    __nv_bfloat16 l1 = __float2bfloat16(v1 - __bfloat162float(h1));
    *reinterpret_cast<__nv_bfloat162*>(H + off) = __halves2bfloat162(h0, h1);
    *reinterpret_cast<__nv_bfloat162*>(L + off) = __halves2bfloat162(l0, l1);
}
// stable bubble-insert: equal keys keep earlier (smaller index) element
__device__ __forceinline__ void ins8(float kd[8], int ki[8], float d, int j) {
    if (d < kd[7]) {
        float nd = d; int nj = j;
#pragma unroll
        for (int k = 0; k < 8; ++k) {
            if (nd < kd[k]) {
                float td = kd[k]; int ti = ki[k];
                kd[k] = nd; ki[k] = nj;
                nd = td; nj = ti;
            }
        }
    }
}
// min of 8 contiguous floats (strict <, first wins on ties)
__device__ __forceinline__ void grpmin(const float* p, float& m, int& mi) {
    float4 v0 = *reinterpret_cast<const float4*>(p);
    float4 v1 = *reinterpret_cast<const float4*>(p + 4);
    m = v0.x; mi = 0;
    if (v0.y < m) { m = v0.y; mi = 1; }
    if (v0.z < m) { m = v0.z; mi = 2; }
    if (v0.w < m) { m = v0.w; mi = 3; }
    if (v1.x < m) { m = v1.x; mi = 4; }
    if (v1.y < m) { m = v1.y; mi = 5; }
    if (v1.z < m) { m = v1.z; mi = 6; }
    if (v1.w < m) { m = v1.w; mi = 7; }
}

// ---------------- unified warp-MMA GEMM, 3-stage cp.async, K-chunk 32 ----------------
// D[m][n] = sum_k A[m][k]*B[n][k], fp32 accum, 3-product bf16 split precision.
// Tile 128x128, K-chunks of 32, 3-stage ring (96KB smem -> 2 CTA/SM), one sync per chunk.
// 8 warps = 2(M)x4(N). Stage: Ah +0, Al +8192, Bh +16384, Bl +24576.
// GATHER: A[e][k] = lrelu((ah+al)[i][k] + (bh+bl)[j][k+384]), i=e>>3, j=knn[e].
// EPI: 0 fp32 (+ACT); 1 max over 8 edge rows -> hi/lo [node][256] (+lrelu);
//      2 distance + fused per-slice top-8 (group-min select); 3 hi/lo with ab remap;
//      4 hi/lo (+ACT).
#define SMEM_SZ 98304
template <int GATHER, int EPI, int ACT>
__global__ __launch_bounds__(256, 2)
void tc_gemm(const __nv_bfloat16* __restrict__ AH, const __nv_bfloat16* __restrict__ AL,
             int aK, const int* __restrict__ knn,
             const __nv_bfloat16* __restrict__ BH, const __nv_bfloat16* __restrict__ BL,
             int bK, const float* __restrict__ bias, const float* __restrict__ nrm,
             float* __restrict__ outF, __nv_bfloat16* __restrict__ outH,
             __nv_bfloat16* __restrict__ outL, int* __restrict__ candI,
             int ldOut, int Ntot, int nch, int zRows) {
    extern __shared__ char smem[];
    const uint32_t sbase = smem_u32(smem);
    const int tid = threadIdx.x, wid = tid >> 5, lane = tid & 31;
    const int warpM = wid & 1, warpN = wid >> 1;
    const int m0 = blockIdx.y * 128, n0 = blockIdx.x * 128;
    const int rbase = blockIdx.z * zRows;

    const int crow = tid >> 1, cby = (tid & 1) * 32;    // cp.async: row, byte offset
    const int arow = tid >> 1, acb = (tid & 1) * 16;    // gather: row, k offset
    const __nv_bfloat16 *pah = nullptr, *pal = nullptr, *pbh = nullptr, *pbl = nullptr;
    if constexpr (GATHER) {
        int e = m0 + arow;
        int i = e >> 3, j = __ldg(&knn[e]);
        pah = AH + (size_t)i * 768;
        pal = AL + (size_t)i * 768;
        pbh = AH + (size_t)j * 768 + 384;
        pbl = AL + (size_t)j * 768 + 384;
    }

    float acc[4][4][4];
#pragma unroll
    for (int a = 0; a < 4; ++a)
#pragma unroll
        for (int b = 0; b < 4; ++b)
#pragma unroll
            for (int c = 0; c < 4; ++c) acc[a][b][c] = 0.f;
    float vA[16];

    auto cpasync = [&](int c) {
        const int k0 = c * 32;
        uint32_t bb = sbase + (c % 3) * 32768;
        uint32_t d0 = sw64(crow, cby), d1 = sw64(crow, cby + 16);
        if constexpr (!GATHER) {
            size_t go = (size_t)(rbase + m0 + crow) * aK + k0 + cby / 2;
            cpa16(bb + d0, AH + go, true);
            cpa16(bb + d1, AH + go + 8, true);
            cpa16(bb + 8192 + d0, AL + go, true);
            cpa16(bb + 8192 + d1, AL + go + 8, true);
        }
        bool p = (n0 + crow) < Ntot;
        size_t gb = (size_t)(rbase + n0 + crow) * bK + k0 + cby / 2;
        cpa16(bb + 16384 + d0, BH + gb, p);
        cpa16(bb + 16384 + d1, BH + gb + 8, p);
        cpa16(bb + 24576 + d0, BL + gb, p);
        cpa16(bb + 24576 + d1, BL + gb + 8, p);
    };
    auto prefetchA = [&](int c) {
        if constexpr (GATHER) {
            const int k0 = c * 32;
#pragma unroll
            for (int g = 0; g < 2; ++g) {
                int k = k0 + acb + g * 8;
                if (k < 336) {
                    uint4 uah = *reinterpret_cast<const uint4*>(pah + k);
                    uint4 ual = *reinterpret_cast<const uint4*>(pal + k);
                    uint4 ubh = *reinterpret_cast<const uint4*>(pbh + k);
                    uint4 ubl = *reinterpret_cast<const uint4*>(pbl + k);
                    const __nv_bfloat16* xh = reinterpret_cast<const __nv_bfloat16*>(&uah);
                    const __nv_bfloat16* xl = reinterpret_cast<const __nv_bfloat16*>(&ual);
                    const __nv_bfloat16* yh = reinterpret_cast<const __nv_bfloat16*>(&ubh);
                    const __nv_bfloat16* yl = reinterpret_cast<const __nv_bfloat16*>(&ubl);
#pragma unroll
                    for (int q = 0; q < 8; ++q)
                        vA[g * 8 + q] = lrelu(
                            (__bfloat162float(xh[q]) + __bfloat162float(xl[q])) +
                            (__bfloat162float(yh[q]) + __bfloat162float(yl[q])));
                } else {
#pragma unroll
                    for (int q = 0; q < 8; ++q) vA[g * 8 + q] = 0.f;
                }
            }
        }
    };
    auto stsA = [&](int c) {
        if constexpr (GATHER) {
            char* base = smem + (c % 3) * 32768;
#pragma unroll
            for (int g = 0; g < 2; ++g)
                store8(base, base + 8192, arow, (acb + g * 8) * 2, &vA[g * 8]);
        }
    };

    // prologue: chunks 0,1 in flight
    cpasync(0);
    CP_COMMIT();
    if (nch > 1) { cpasync(1); CP_COMMIT(); }
    prefetchA(0);
    stsA(0);
    if (nch > 1) { prefetchA(1); stsA(1); }

    const int lr = lane & 15, lk = (lane >> 4) * 16;   // bytes
    for (int c = 0; c < nch; ++c) {
        if (c + 1 < nch) { CP_WAIT1(); } else { CP_WAIT0(); }
        __syncthreads();   // chunk c visible; all warps done reading stage (c-1)%3
        if (c + 2 < nch) {
            cpasync(c + 2);
            CP_COMMIT();
            prefetchA(c + 2);
        }
        const uint32_t bb = sbase + (c % 3) * 32768;
        const uint32_t sAh = bb, sAl = bb + 8192, sBh = bb + 16384, sBl = bb + 24576;
#pragma unroll
        for (int ks = 0; ks < 2; ++ks) {
            const int kb = ks * 32 + lk;
            uint32_t ah[4][4], al[4][4], bh[2][4], bl[2][4];
#pragma unroll
            for (int mt = 0; mt < 4; ++mt) {
                int row = warpM * 64 + mt * 16 + lr;
                uint32_t o = sw64(row, kb);
                ldsm4(ah[mt], sAh + o);
                ldsm4(al[mt], sAl + o);
            }
#pragma unroll
            for (int nt = 0; nt < 2; ++nt) {
                int row = warpN * 32 + nt * 16 + lr;
                uint32_t o = sw64(row, kb);
                ldsm4(bh[nt], sBh + o);
                ldsm4(bl[nt], sBl + o);
            }
#pragma unroll
            for (int mt = 0; mt < 4; ++mt)
#pragma unroll
                for (int nt8 = 0; nt8 < 4; ++nt8) {
                    int nt16 = nt8 >> 1, s = nt8 & 1;
                    mma_bf16(acc[mt][nt8], ah[mt], bh[nt16][s], bh[nt16][s + 2]);
                    mma_bf16(acc[mt][nt8], ah[mt], bl[nt16][s], bl[nt16][s + 2]);
                    mma_bf16(acc[mt][nt8], al[mt], bh[nt16][s], bh[nt16][s + 2]);
                }
        }
        if (c + 2 < nch) stsA(c + 2);   // stage (c-1)%3 A-region; safe post-sync
    }

    // ---------------- epilogue ----------------
    if constexpr (EPI == 2) {
        // distance + fused per-slice top-8 (group-min extraction)
        __syncthreads();
        float* tile = reinterpret_cast<float*>(smem);   // 128 x 132 floats
#pragma unroll
        for (int mt = 0; mt < 4; ++mt) {
            int r0 = warpM * 64 + mt * 16 + (lane >> 2);
            float ni0 = nrm[rbase + m0 + r0];
            float ni1 = nrm[rbase + m0 + r0 + 8];
#pragma unroll
            for (int nt8 = 0; nt8 < 4; ++nt8) {
                int n = warpN * 32 + nt8 * 8 + (lane & 3) * 2;
                float nj0 = nrm[rbase + n0 + n], nj1 = nrm[rbase + n0 + n + 1];
                tile[r0 * 132 + n]           = ni0 + nj0 - 2.f * acc[mt][nt8][0];
                tile[r0 * 132 + n + 1]       = ni0 + nj1 - 2.f * acc[mt][nt8][1];
                tile[(r0 + 8) * 132 + n]     = ni1 + nj0 - 2.f * acc[mt][nt8][2];
                tile[(r0 + 8) * 132 + n + 1] = ni1 + nj1 - 2.f * acc[mt][nt8][3];
            }
        }
        __syncthreads();
        int row = tid >> 1, half = tid & 1;
        float* tr = tile + row * 132 + half * 64;
        // 8 group mins
        float gm[8]; int gi[8];
#pragma unroll
        for (int g = 0; g < 8; ++g) {
            float m; int mi;
            grpmin(tr + g * 8, m, mi);
            gm[g] = m; gi[g] = g * 8 + mi;
        }
        // 8 extraction rounds (ascending distance; ties -> smaller index since
        // group order = column order and grpmin keeps first)
        float kd[8]; int ki[8];
#pragma unroll
        for (int r = 0; r < 8; ++r) {
            float m = gm[0]; int g = 0;
#pragma unroll
            for (int t = 1; t < 8; ++t) if (gm[t] < m) { m = gm[t]; g = t; }
            int src = gi[0];
#pragma unroll
            for (int t = 1; t < 8; ++t) if (t == g) src = gi[t];
            kd[r] = m;
            ki[r] = half * 64 + src;
            tr[src] = FLT_MAX;
            float nm; int nmi;
            grpmin(tr + g * 8, nm, nmi);
#pragma unroll
            for (int t = 0; t < 8; ++t) if (t == g) { gm[t] = nm; gi[t] = g * 8 + nmi; }
        }
        // merge partner halves (half 0 first -> ties prefer smaller column)
        float pdv[8]; int piv[8];
#pragma unroll
        for (int k = 0; k < 8; ++k) {
            pdv[k] = __shfl_xor_sync(0xffffffffu, kd[k], 1);
            piv[k] = __shfl_xor_sync(0xffffffffu, ki[k], 1);
        }
        if (half == 0) {
#pragma unroll
            for (int k = 0; k < 8; ++k) ins8(kd, ki, pdv[k], piv[k]);
            size_t base = (size_t)(rbase + m0 + row) * 32 + blockIdx.x * 8;
#pragma unroll
            for (int k = 0; k < 8; ++k) {
                outF[base + k] = kd[k];
                candI[base + k] = n0 + ki[k];
            }
        }
    } else if constexpr (EPI == 1) {
#pragma unroll
        for (int mt = 0; mt < 4; ++mt) {
            int nodeA = (m0 + warpM * 64 + mt * 16) >> 3;
#pragma unroll
            for (int nt8 = 0; nt8 < 4; ++nt8) {
                float c0 = acc[mt][nt8][0], c1 = acc[mt][nt8][1];
                float c2 = acc[mt][nt8][2], c3 = acc[mt][nt8][3];
#pragma unroll
                for (int m = 4; m <= 16; m <<= 1) {
                    c0 = fmaxf(c0, __shfl_xor_sync(0xffffffffu, c0, m));
                    c1 = fmaxf(c1, __shfl_xor_sync(0xffffffffu, c1, m));
                    c2 = fmaxf(c2, __shfl_xor_sync(0xffffffffu, c2, m));
                    c3 = fmaxf(c3, __shfl_xor_sync(0xffffffffu, c3, m));
                }
                if (lane < 4) {
                    int n = n0 + warpN * 32 + nt8 * 8 + lane * 2;
                    float b0 = bias[n], b1 = bias[n + 1];
                    wpair(outH, outL, (size_t)nodeA * ldOut + n,
                          lrelu(c0 + b0), lrelu(c1 + b1));
                    wpair(outH, outL, (size_t)(nodeA + 1) * ldOut + n,
                          lrelu(c2 + b0), lrelu(c3 + b1));
                }
            }
        }
    } else {
#pragma unroll
        for (int mt = 0; mt < 4; ++mt) {
            int rA = m0 + warpM * 64 + mt * 16 + (lane >> 2);
#pragma unroll
            for (int nt8 = 0; nt8 < 4; ++nt8) {
                int n = n0 + warpN * 32 + nt8 * 8 + (lane & 3) * 2;
                if (n >= Ntot) continue;
                float a0 = acc[mt][nt8][0], a1 = acc[mt][nt8][1];
                float a2 = acc[mt][nt8][2], a3 = acc[mt][nt8][3];
                float b0 = bias[n], b1 = bias[n + 1];
                float v0 = a0 + b0, v1 = a1 + b1, v2 = a2 + b0, v3 = a3 + b1;
                if (ACT) { v0 = lrelu(v0); v1 = lrelu(v1); v2 = lrelu(v2); v3 = lrelu(v3); }
                if constexpr (EPI == 0) {
                    *reinterpret_cast<float2*>(outF + (size_t)rA * ldOut + n) =
                        make_float2(v0, v1);
                    *reinterpret_cast<float2*>(outF + (size_t)(rA + 8) * ldOut + n) =
                        make_float2(v2, v3);
                } else {
                    int cm = n;
                    if constexpr (EPI == 3) { if (n >= 336) cm = n + 48; }
                    wpair(outH, outL, (size_t)rA * ldOut + cm, v0, v1);
                    wpair(outH, outL, (size_t)(rA + 8) * ldOut + cm, v2, v3);
                }
            }
        }
    }
}

// ---------------- knn merge: 4 slices x 8 candidates -> top-8 ----------------
__global__ void knnmerge_kernel(const float* __restrict__ cd, const int* __restrict__ ci,
                                int* __restrict__ knn) {
    int r = blockIdx.x * 256 + threadIdx.x;
    if (r >= BN_) return;
    float kd[8]; int ki[8];
#pragma unroll
    for (int k = 0; k < 8; ++k) { kd[k] = FLT_MAX; ki[k] = -1; }
    const float* pd = cd + (size_t)r * 32;
    const int* pi = ci + (size_t)r * 32;
#pragma unroll 4
    for (int s = 0; s < 32; ++s) ins8(kd, ki, pd[s], pi[s]);
    int b = r >> 9;
#pragma unroll
    for (int k = 0; k < 8; ++k) knn[r * 8 + k] = b * 512 + ki[k];
}

// ---------------- split / prep kernels ----------------
__global__ void splitx_kernel(const float* __restrict__ x, __nv_bfloat16* __restrict__ xh,
                              __nv_bfloat16* __restrict__ xl) {
    int idx = blockIdx.x * blockDim.x + threadIdx.x;
    if (idx >= BN_ * 64) return;
    int i = idx >> 6, f = idx & 63;
    float v = (f < 6) ? x[i * 6 + f] : 0.f;
    __nv_bfloat16 h = __float2bfloat16(v);
    xh[idx] = h;
    xl[idx] = __float2bfloat16(v - __bfloat162float(h));
}

__global__ void splitw_kernel(const float* __restrict__ W, __nv_bfloat16* __restrict__ bh,
                              __nv_bfloat16* __restrict__ bl, int K, int N, int Kpad) {
    int idx = blockIdx.x * blockDim.x + threadIdx.x;
    if (idx >= N * Kpad) return;
    int n = idx / Kpad, k = idx % Kpad;
    float v = (k < K) ? W[(size_t)k * N + n] : 0.f;
    __nv_bfloat16 h = __float2bfloat16(v);
    bh[idx] = h;
    bl[idx] = __float2bfloat16(v - __bfloat162float(h));
}

__global__ void splitw1_kernel(const float* __restrict__ w1, const float* __restrict__ b1,
                               __nv_bfloat16* __restrict__ bh, __nv_bfloat16* __restrict__ bl,
                               float* __restrict__ bcomb, int F, int Kpad) {
    int idx = blockIdx.x * blockDim.x + threadIdx.x;
    if (idx < 672) bcomb[idx] = (idx < H_) ? b1[idx] : 0.f;
    if (idx >= 672 * Kpad) return;
    int n = idx / Kpad, f = idx % Kpad;
    float v = 0.f;
    if (f < F)
        v = (n < H_) ? (w1[f * H_ + n] - w1[(F + f) * H_ + n])
                     : w1[(F + f) * H_ + (n - H_)];
    __nv_bfloat16 h = __float2bfloat16(v);
    bh[idx] = h;
    bl[idx] = __float2bfloat16(v - __bfloat162float(h));
}

__global__ void concat_kernel(const float* __restrict__ x,
                              const __nv_bfloat16* __restrict__ xoh,
                              const __nv_bfloat16* __restrict__ xol,
                              __nv_bfloat16* __restrict__ ch,
                              __nv_bfloat16* __restrict__ cl) {
    int idx = blockIdx.x * blockDim.x + threadIdx.x;
    if (idx >= BN_ * 1088) return;
    int i = idx / 1088, f = idx % 1088;
    if (f < 6) {
        float v = x[i * 6 + f];
        __nv_bfloat16 h = __float2bfloat16(v);
        ch[idx] = h;
        cl[idx] = __float2bfloat16(v - __bfloat162float(h));
    } else if (f < 1030) {
        int g = f - 6;
        int l = g >> 8, c = g & 255;
        size_t so = (size_t)l * BN_ * 256 + (size_t)i * 256 + c;
        ch[idx] = xoh[so];
        cl[idx] = xol[so];
    } else {
        ch[idx] = __float2bfloat16(0.f);
        cl[idx] = __float2bfloat16(0.f);
    }
}

__global__ void zfill_t(__nv_bfloat16* __restrict__ th, __nv_bfloat16* __restrict__ tl) {
    int idx = blockIdx.x * blockDim.x + threadIdx.x;
    if (idx >= BN_ * 48) return;
    int i = idx / 48, p = idx % 48;
    th[(size_t)i * 384 + 336 + p] = __float2bfloat16(0.f);
    tl[(size_t)i * 384 + 336 + p] = __float2bfloat16(0.f);
}

// ---------------- small kernels ----------------
__global__ void norm_kernel(const __nv_bfloat16* __restrict__ xh,
                            const __nv_bfloat16* __restrict__ xl,
                            float* __restrict__ nrm, int F) {
    int i = blockIdx.x * blockDim.x + threadIdx.x;
    if (i >= BN_) return;
    float s = 0.f;
    for (int f = 0; f < F; ++f) {
        float v = __bfloat162float(xh[(size_t)i * F + f]) +
                  __bfloat162float(xl[(size_t)i * F + f]);
        s += v * v;
    }
    nrm[i] = s;
}

__global__ void pool_kernel(const float* __restrict__ m, float* __restrict__ g) {
    int b = blockIdx.x, c = threadIdx.x;
    float s = 0.f;
    for (int n = 0; n < N_; ++n) s += m[(size_t)(b * N_ + n) * C_ + c];
    g[b * C_ + c] = s * (1.f / (float)N_);
}

__global__ void head_kernel(const float* __restrict__ g, const float* __restrict__ w1,
                            const float* __restrict__ b1, const float* __restrict__ w2,
                            const float* __restrict__ b2, float* __restrict__ out) {
    __shared__ float sg[256];
    __shared__ float sh[128];
    int b = blockIdx.x, t = threadIdx.x;
    sg[t] = g[b * 256 + t];
    sg[t + 128] = g[b * 256 + 128 + t];
    __syncthreads();
    float s = b1[t];
    for (int f = 0; f < 256; ++f) s += sg[f] * w1[f * 128 + t];
    sh[t] = lrelu(s);
    __syncthreads();
    if (t < 3) {
        float o = b2[t];
        for (int c = 0; c < 128; ++c) o += sh[c] * w2[c * 3 + t];
        out[b * 3 + t] = o;
    }
}

// ---------------- host ----------------
extern "C" void kernel_launch(void* const* d_in, const int* in_sizes, int n_in,
                              void* d_out, int out_size) {
    const float* x = (const float*)d_in[0];
    const float *cw1[4], *cb1[4], *cw2[4], *cb2[4];
    for (int L = 0; L < 4; ++L) {
        cw1[L] = (const float*)d_in[3 + 4 * L];
        cb1[L] = (const float*)d_in[4 + 4 * L];
        cw2[L] = (const float*)d_in[5 + 4 * L];
        cb2[L] = (const float*)d_in[6 + 4 * L];
    }
    const float* m1w1 = (const float*)d_in[19];
    const float* m1b1 = (const float*)d_in[20];
    const float* m1w2 = (const float*)d_in[21];
    const float* m1b2 = (const float*)d_in[22];
    const float* m2w1 = (const float*)d_in[23];
    const float* m2b1 = (const float*)d_in[24];
    const float* m2w2 = (const float*)d_in[25];
    const float* m2b2 = (const float*)d_in[26];
    float* out = (float*)d_out;

    float *p_nrm, *p_m, *p_pool, *p_bc, *p_cd;
    int *p_knn, *p_ci;
    __nv_bfloat16 *p_xsh, *p_xsl, *p_xoh, *p_xol, *p_abh, *p_abl;
    __nv_bfloat16 *p_cath, *p_catl, *p_th, *p_tl, *p_bh1, *p_bl1, *p_bh2, *p_bl2;
    cudaGetSymbolAddress((void**)&p_knn, g_knn);
    cudaGetSymbolAddress((void**)&p_nrm, g_norm);
    cudaGetSymbolAddress((void**)&p_m, g_m);
    cudaGetSymbolAddress((void**)&p_pool, g_pool);
    cudaGetSymbolAddress((void**)&p_bc, g_bcomb);
    cudaGetSymbolAddress((void**)&p_cd, g_candd);
    cudaGetSymbolAddress((void**)&p_ci, g_candi);
    cudaGetSymbolAddress((void**)&p_xsh, g_xsh);
    cudaGetSymbolAddress((void**)&p_xsl, g_xsl);
    cudaGetSymbolAddress((void**)&p_xoh, g_xoh);
    cudaGetSymbolAddress((void**)&p_xol, g_xol);
    cudaGetSymbolAddress((void**)&p_abh, g_abh);
    cudaGetSymbolAddress((void**)&p_abl, g_abl);
    cudaGetSymbolAddress((void**)&p_cath, g_cath);
    cudaGetSymbolAddress((void**)&p_catl, g_catl);
    cudaGetSymbolAddress((void**)&p_th, g_th);
    cudaGetSymbolAddress((void**)&p_tl, g_tl);
    cudaGetSymbolAddress((void**)&p_bh1, g_bh1);
    cudaGetSymbolAddress((void**)&p_bl1, g_bl1);
    cudaGetSymbolAddress((void**)&p_bh2, g_bh2);
    cudaGetSymbolAddress((void**)&p_bl2, g_bl2);

    cudaFuncSetAttribute(tc_gemm<0, 2, 0>, cudaFuncAttributeMaxDynamicSharedMemorySize, SMEM_SZ);
    cudaFuncSetAttribute(tc_gemm<0, 3, 0>, cudaFuncAttributeMaxDynamicSharedMemorySize, SMEM_SZ);
    cudaFuncSetAttribute(tc_gemm<1, 1, 0>, cudaFuncAttributeMaxDynamicSharedMemorySize, SMEM_SZ);
    cudaFuncSetAttribute(tc_gemm<0, 4, 1>, cudaFuncAttributeMaxDynamicSharedMemorySize, SMEM_SZ);
    cudaFuncSetAttribute(tc_gemm<0, 0, 1>, cudaFuncAttributeMaxDynamicSharedMemorySize, SMEM_SZ);

    splitx_kernel<<<(BN_ * 64 + 255) / 256, 256>>>(x, p_xsh, p_xsl);
    zfill_t<<<(BN_ * 48 + 255) / 256, 256>>>(p_th, p_tl);

    for (int L = 0; L < 4; ++L) {
        const __nv_bfloat16* xh = L ? p_xoh + (size_t)(L - 1) * BN_ * 256 : p_xsh;
        const __nv_bfloat16* xl = L ? p_xol + (size_t)(L - 1) * BN_ * 256 : p_xsl;
        int aK = L ? 256 : 64;
        int F = L ? 256 : 6;
        int nchX = L ? 8 : 1;   // K=6 fits in one 32-chunk for layer 0

        norm_kernel<<<BN_ / 256, 256>>>(xh, xl, p_nrm, aK);
        // distance GEMM with fused per-slice top-8
        tc_gemm<0, 2, 0><<<dim3(4, 4, B_), 256, SMEM_SZ>>>(
            xh, xl, aK, nullptr, xh, xl, aK, nullptr, p_nrm,
            p_cd, nullptr, nullptr, p_ci, N_, N_, nchX, N_);
        knnmerge_kernel<<<BN_ / 256, 256>>>(p_cd, p_ci, p_knn);
        splitw1_kernel<<<(672 * aK + 255) / 256, 256>>>(cw1[L], cb1[L], p_bh1, p_bl1,
                                                        p_bc, F, aK);
        tc_gemm<0, 3, 0><<<dim3(6, BN_ / 128), 256, SMEM_SZ>>>(
            xh, xl, aK, nullptr, p_bh1, p_bl1, aK, p_bc, nullptr,
            nullptr, p_abh, p_abl, nullptr, 768, 672, nchX, 0);
        splitw_kernel<<<(256 * 384 + 255) / 256, 256>>>(cw2[L], p_bh2, p_bl2, H_, C_, 384);
        // edge GEMM: K=336 -> 11 chunks (cols 336-351 zeroed by gather guard;
        // weight rows >=336 zero-padded)
        tc_gemm<1, 1, 0><<<dim3(2, (BN_ * K_) / 128), 256, SMEM_SZ>>>(
            p_abh, p_abl, 768, p_knn, p_bh2, p_bl2, 384, cb2[L], nullptr,
            nullptr, p_xoh + (size_t)L * BN_ * 256, p_xol + (size_t)L * BN_ * 256,
            nullptr, 256, 256, 11, 0);
    }

    concat_kernel<<<(BN_ * 1088 + 255) / 256, 256>>>(x, p_xoh, p_xol, p_cath, p_catl);
    splitw_kernel<<<(336 * 1088 + 255) / 256, 256>>>(m1w1, p_bh1, p_bl1, 1030, H_, 1088);
    // mlp1: K=1030 -> 33 chunks (cat cols 1030-1055 and weight rows zero-padded)
    tc_gemm<0, 4, 1><<<dim3(3, BN_ / 128), 256, SMEM_SZ>>>(
        p_cath, p_catl, 1088, nullptr, p_bh1, p_bl1, 1088, m1b1, nullptr,
        nullptr, p_th, p_tl, nullptr, 384, H_, 33, 0);
    splitw_kernel<<<(256 * 384 + 255) / 256, 256>>>(m1w2, p_bh2, p_bl2, H_, C_, 384);
    tc_gemm<0, 0, 1><<<dim3(2, BN_ / 128), 256, SMEM_SZ>>>(
        p_th, p_tl, 384, nullptr, p_bh2, p_bl2, 384, m1b2, nullptr,
        p_m, nullptr, nullptr, nullptr, 256, 256, 12, 0);
    pool_kernel<<<B_, 256>>>(p_m, p_pool);
    head_kernel<<<B_, 128>>>(p_pool, m2w1, m2b1, m2w2, m2b2, out);
}

// round 17
// speedup vs baseline: 1.4897x; 1.4897x over previous
#include <cuda_runtime.h>
#include <cuda_bf16.h>
#include <cstdint>
#include <cfloat>

#define B_    64
#define N_    512
#define BN_   32768
#define K_    8
#define H_    336
#define C_    256

// ---------------- scratch (static device memory) ----------------
__device__ int   g_knn[BN_ * K_];
__device__ float g_norm[BN_];
__device__ float g_m[(size_t)BN_ * C_];
__device__ float g_pool[B_ * C_];
__device__ float g_bcomb[672];
__device__ float g_candd[(size_t)BN_ * 32];
__device__ int   g_candi[(size_t)BN_ * 32];
__device__ __nv_bfloat16 g_xsh[BN_ * 64],  g_xsl[BN_ * 64];
__device__ __nv_bfloat16 g_xoh[4 * (size_t)BN_ * C_], g_xol[4 * (size_t)BN_ * C_];
__device__ __nv_bfloat16 g_abh[(size_t)BN_ * 768], g_abl[(size_t)BN_ * 768];
__device__ __nv_bfloat16 g_cath[(size_t)BN_ * 1088], g_catl[(size_t)BN_ * 1088];
__device__ __nv_bfloat16 g_th[(size_t)BN_ * 384], g_tl[(size_t)BN_ * 384];
__device__ __nv_bfloat16 g_bh1[672 * 1088], g_bl1[672 * 1088];
__device__ __nv_bfloat16 g_bh2[256 * 384],  g_bl2[256 * 384];

__device__ __forceinline__ float lrelu(float v) { return v >= 0.f ? v : 0.01f * v; }
__device__ __forceinline__ uint32_t sw64(int row, int b) {
    return (uint32_t)(row * 64 + (b ^ (((row >> 1) & 3) << 4)));
}
__device__ __forceinline__ uint32_t smem_u32(const void* p) {
    uint32_t a;
    asm("{ .reg .u64 t; cvta.to.shared.u64 t, %1; cvt.u32.u64 %0, t; }" : "=r"(a) : "l"(p));
    return a;
}
__device__ __forceinline__ void ldsm4(uint32_t r[4], uint32_t addr) {
    asm volatile("ldmatrix.sync.aligned.m8n8.x4.shared.b16 {%0,%1,%2,%3}, [%4];"
                 : "=r"(r[0]), "=r"(r[1]), "=r"(r[2]), "=r"(r[3]) : "r"(addr));
}
__device__ __forceinline__ void mma_bf16(float c[4], const uint32_t a[4],
                                         uint32_t b0, uint32_t b1) {
    asm volatile(
        "mma.sync.aligned.m16n8k16.row.col.f32.bf16.bf16.f32 "
        "{%0,%1,%2,%3}, {%4,%5,%6,%7}, {%8,%9}, {%0,%1,%2,%3};"
        : "+f"(c[0]), "+f"(c[1]), "+f"(c[2]), "+f"(c[3])
        : "r"(a[0]), "r"(a[1]), "r"(a[2]), "r"(a[3]), "r"(b0), "r"(b1));
}
__device__ __forceinline__ void cpa16(uint32_t dst, const void* src, bool pred) {
    int sz = pred ? 16 : 0;
    asm volatile("cp.async.cg.shared.global [%0], [%1], 16, %2;"
                 :: "r"(dst), "l"(src), "r"(sz));
}
#define CP_COMMIT() asm volatile("cp.async.commit_group;" ::: "memory")
#define CP_WAIT0()  asm volatile("cp.async.wait_group 0;" ::: "memory")
#define CP_WAIT1()  asm volatile("cp.async.wait_group 1;" ::: "memory")

__device__ __forceinline__ void store8(char* sh, char* sl, int row, int colbyte,
                                       const float* v) {
    alignas(16) __nv_bfloat16 h[8];
    alignas(16) __nv_bfloat16 l[8];
#pragma unroll
    for (int q = 0; q < 8; ++q) {
        h[q] = __float2bfloat16(v[q]);
        l[q] = __float2bfloat16(v[q] - __bfloat162float(h[q]));
    }
    uint32_t so = sw64(row, colbyte);
    *reinterpret_cast<uint4*>(sh + so) = *reinterpret_cast<const uint4*>(h);
    *reinterpret_cast<uint4*>(sl + so) = *reinterpret_cast<const uint4*>(l);
}
__device__ __forceinline__ void wpair(__nv_bfloat16* H, __nv_bfloat16* L, size_t off,
                                      float v0, float v1) {
    __nv_bfloat16 h0 = __float2bfloat16(v0), h1 = __float2bfloat16(v1);
    __nv_bfloat16 l0 = __float2bfloat16(v0 - __bfloat162float(h0));
    __nv_bfloat16 l1 = __float2bfloat16(v1 - __bfloat162float(h1));
    *reinterpret_cast<__nv_bfloat162*>(H + off) = __halves2bfloat162(h0, h1);
    *reinterpret_cast<__nv_bfloat162*>(L + off) = __halves2bfloat162(l0, l1);
}
// stable bubble-insert: equal keys keep earlier (smaller index) element
__device__ __forceinline__ void ins8(float kd[8], int ki[8], float d, int j) {
    if (d < kd[7]) {
        float nd = d; int nj = j;
#pragma unroll
        for (int k = 0; k < 8; ++k) {
            if (nd < kd[k]) {
                float td = kd[k]; int ti = ki[k];
                kd[k] = nd; ki[k] = nj;
                nd = td; nj = ti;
            }
        }
    }
}
// min of 8 contiguous floats (strict <, first wins on ties)
__device__ __forceinline__ void grpmin(const float* p, float& m, int& mi) {
    float4 v0 = *reinterpret_cast<const float4*>(p);
    float4 v1 = *reinterpret_cast<const float4*>(p + 4);
    m = v0.x; mi = 0;
    if (v0.y < m) { m = v0.y; mi = 1; }
    if (v0.z < m) { m = v0.z; mi = 2; }
    if (v0.w < m) { m = v0.w; mi = 3; }
    if (v1.x < m) { m = v1.x; mi = 4; }
    if (v1.y < m) { m = v1.y; mi = 5; }
    if (v1.z < m) { m = v1.z; mi = 6; }
    if (v1.w < m) { m = v1.w; mi = 7; }
}

// ---------------- unified warp-MMA GEMM, 3-stage cp.async, K-chunk 32 ----------------
// D[m][n] = sum_k A[m][k]*B[n][k], fp32 accum, 3-product bf16 split precision.
// Tile 128x128, K-chunks of 32, 3-stage ring (96KB smem -> 2 CTA/SM), one sync per chunk.
// 8 warps = 2(M)x4(N). Stage: Ah +0, Al +8192, Bh +16384, Bl +24576.
// GATHER: A[e][k] = lrelu((ah+al)[i][k] + (bh+bl)[j][k+384]), i=e>>3, j=knn[e].
// EPI: 0 fp32 (+ACT); 1 max over 8 edge rows -> hi/lo [node][256] (+lrelu);
//      2 distance + fused per-slice top-8 (group-min select); 3 hi/lo with ab remap;
//      4 hi/lo (+ACT).
#define SMEM_SZ 98304
template <int GATHER, int EPI, int ACT>
__global__ __launch_bounds__(256, 2)
void tc_gemm(const __nv_bfloat16* __restrict__ AH, const __nv_bfloat16* __restrict__ AL,
             int aK, const int* __restrict__ knn,
             const __nv_bfloat16* __restrict__ BH, const __nv_bfloat16* __restrict__ BL,
             int bK, const float* __restrict__ bias, const float* __restrict__ nrm,
             float* __restrict__ outF, __nv_bfloat16* __restrict__ outH,
             __nv_bfloat16* __restrict__ outL, int* __restrict__ candI,
             int ldOut, int Ntot, int nch, int zRows) {
    extern __shared__ char smem[];
    const uint32_t sbase = smem_u32(smem);
    const int tid = threadIdx.x, wid = tid >> 5, lane = tid & 31;
    const int warpM = wid & 1, warpN = wid >> 1;
    const int m0 = blockIdx.y * 128, n0 = blockIdx.x * 128;
    const int rbase = blockIdx.z * zRows;

    const int crow = tid >> 1, cby = (tid & 1) * 32;    // cp.async: row, byte offset
    const int arow = tid >> 1, acb = (tid & 1) * 16;    // gather: row, k offset
    const __nv_bfloat16 *pah = nullptr, *pal = nullptr, *pbh = nullptr, *pbl = nullptr;
    if constexpr (GATHER) {
        int e = m0 + arow;
        int i = e >> 3, j = __ldg(&knn[e]);
        pah = AH + (size_t)i * 768;
        pal = AL + (size_t)i * 768;
        pbh = AH + (size_t)j * 768 + 384;
        pbl = AL + (size_t)j * 768 + 384;
    }

    float acc[4][4][4];
#pragma unroll
    for (int a = 0; a < 4; ++a)
#pragma unroll
        for (int b = 0; b < 4; ++b)
#pragma unroll
            for (int c = 0; c < 4; ++c) acc[a][b][c] = 0.f;
    float vA[16];

    auto cpasync = [&](int c) {
        const int k0 = c * 32;
        uint32_t bb = sbase + (c % 3) * 32768;
        uint32_t d0 = sw64(crow, cby), d1 = sw64(crow, cby + 16);
        if constexpr (!GATHER) {
            size_t go = (size_t)(rbase + m0 + crow) * aK + k0 + cby / 2;
            cpa16(bb + d0, AH + go, true);
            cpa16(bb + d1, AH + go + 8, true);
            cpa16(bb + 8192 + d0, AL + go, true);
            cpa16(bb + 8192 + d1, AL + go + 8, true);
        }
        bool p = (n0 + crow) < Ntot;
        size_t gb = (size_t)(rbase + n0 + crow) * bK + k0 + cby / 2;
        cpa16(bb + 16384 + d0, BH + gb, p);
        cpa16(bb + 16384 + d1, BH + gb + 8, p);
        cpa16(bb + 24576 + d0, BL + gb, p);
        cpa16(bb + 24576 + d1, BL + gb + 8, p);
    };
    auto prefetchA = [&](int c) {
        if constexpr (GATHER) {
            const int k0 = c * 32;
#pragma unroll
            for (int g = 0; g < 2; ++g) {
                int k = k0 + acb + g * 8;
                if (k < 336) {
                    uint4 uah = *reinterpret_cast<const uint4*>(pah + k);
                    uint4 ual = *reinterpret_cast<const uint4*>(pal + k);
                    uint4 ubh = *reinterpret_cast<const uint4*>(pbh + k);
                    uint4 ubl = *reinterpret_cast<const uint4*>(pbl + k);
                    const __nv_bfloat16* xh = reinterpret_cast<const __nv_bfloat16*>(&uah);
                    const __nv_bfloat16* xl = reinterpret_cast<const __nv_bfloat16*>(&ual);
                    const __nv_bfloat16* yh = reinterpret_cast<const __nv_bfloat16*>(&ubh);
                    const __nv_bfloat16* yl = reinterpret_cast<const __nv_bfloat16*>(&ubl);
#pragma unroll
                    for (int q = 0; q < 8; ++q)
                        vA[g * 8 + q] = lrelu(
                            (__bfloat162float(xh[q]) + __bfloat162float(xl[q])) +
                            (__bfloat162float(yh[q]) + __bfloat162float(yl[q])));
                } else {
#pragma unroll
                    for (int q = 0; q < 8; ++q) vA[g * 8 + q] = 0.f;
                }
            }
        }
    };
    auto stsA = [&](int c) {
        if constexpr (GATHER) {
            char* base = smem + (c % 3) * 32768;
#pragma unroll
            for (int g = 0; g < 2; ++g)
                store8(base, base + 8192, arow, (acb + g * 8) * 2, &vA[g * 8]);
        }
    };

    // prologue: chunks 0,1 in flight
    cpasync(0);
    CP_COMMIT();
    if (nch > 1) { cpasync(1); CP_COMMIT(); }
    prefetchA(0);
    stsA(0);
    if (nch > 1) { prefetchA(1); stsA(1); }

    const int lr = lane & 15, lk = (lane >> 4) * 16;   // bytes
    for (int c = 0; c < nch; ++c) {
        if (c + 1 < nch) { CP_WAIT1(); } else { CP_WAIT0(); }
        __syncthreads();   // chunk c visible; all warps done reading stage (c-1)%3
        if (c + 2 < nch) {
            cpasync(c + 2);
            CP_COMMIT();
            prefetchA(c + 2);
        }
        const uint32_t bb = sbase + (c % 3) * 32768;
        const uint32_t sAh = bb, sAl = bb + 8192, sBh = bb + 16384, sBl = bb + 24576;
#pragma unroll
        for (int ks = 0; ks < 2; ++ks) {
            const int kb = ks * 32 + lk;
            uint32_t ah[4][4], al[4][4], bh[2][4], bl[2][4];
#pragma unroll
            for (int mt = 0; mt < 4; ++mt) {
                int row = warpM * 64 + mt * 16 + lr;
                uint32_t o = sw64(row, kb);
                ldsm4(ah[mt], sAh + o);
                ldsm4(al[mt], sAl + o);
            }
#pragma unroll
            for (int nt = 0; nt < 2; ++nt) {
                int row = warpN * 32 + nt * 16 + lr;
                uint32_t o = sw64(row, kb);
                ldsm4(bh[nt], sBh + o);
                ldsm4(bl[nt], sBl + o);
            }
#pragma unroll
            for (int mt = 0; mt < 4; ++mt)
#pragma unroll
                for (int nt8 = 0; nt8 < 4; ++nt8) {
                    int nt16 = nt8 >> 1, s = nt8 & 1;
                    mma_bf16(acc[mt][nt8], ah[mt], bh[nt16][s], bh[nt16][s + 2]);
                    mma_bf16(acc[mt][nt8], ah[mt], bl[nt16][s], bl[nt16][s + 2]);
                    mma_bf16(acc[mt][nt8], al[mt], bh[nt16][s], bh[nt16][s + 2]);
                }
        }
        if (c + 2 < nch) stsA(c + 2);   // stage (c-1)%3 A-region; safe post-sync
    }

    // ---------------- epilogue ----------------
    if constexpr (EPI == 2) {
        // distance + fused per-slice top-8 (group-min extraction)
        __syncthreads();
        float* tile = reinterpret_cast<float*>(smem);   // 128 x 132 floats
#pragma unroll
        for (int mt = 0; mt < 4; ++mt) {
            int r0 = warpM * 64 + mt * 16 + (lane >> 2);
            float ni0 = nrm[rbase + m0 + r0];
            float ni1 = nrm[rbase + m0 + r0 + 8];
#pragma unroll
            for (int nt8 = 0; nt8 < 4; ++nt8) {
                int n = warpN * 32 + nt8 * 8 + (lane & 3) * 2;
                float nj0 = nrm[rbase + n0 + n], nj1 = nrm[rbase + n0 + n + 1];
                tile[r0 * 132 + n]           = ni0 + nj0 - 2.f * acc[mt][nt8][0];
                tile[r0 * 132 + n + 1]       = ni0 + nj1 - 2.f * acc[mt][nt8][1];
                tile[(r0 + 8) * 132 + n]     = ni1 + nj0 - 2.f * acc[mt][nt8][2];
                tile[(r0 + 8) * 132 + n + 1] = ni1 + nj1 - 2.f * acc[mt][nt8][3];
            }
        }
        __syncthreads();
        int row = tid >> 1, half = tid & 1;
        float* tr = tile + row * 132 + half * 64;
        // 8 group mins
        float gm[8]; int gi[8];
#pragma unroll
        for (int g = 0; g < 8; ++g) {
            float m; int mi;
            grpmin(tr + g * 8, m, mi);
            gm[g] = m; gi[g] = g * 8 + mi;
        }
        // 8 extraction rounds (ascending distance; ties -> smaller index since
        // group order = column order and grpmin keeps first)
        float kd[8]; int ki[8];
#pragma unroll
        for (int r = 0; r < 8; ++r) {
            float m = gm[0]; int g = 0;
#pragma unroll
            for (int t = 1; t < 8; ++t) if (gm[t] < m) { m = gm[t]; g = t; }
            int src = gi[0];
#pragma unroll
            for (int t = 1; t < 8; ++t) if (t == g) src = gi[t];
            kd[r] = m;
            ki[r] = half * 64 + src;
            tr[src] = FLT_MAX;
            float nm; int nmi;
            grpmin(tr + g * 8, nm, nmi);
#pragma unroll
            for (int t = 0; t < 8; ++t) if (t == g) { gm[t] = nm; gi[t] = g * 8 + nmi; }
        }
        // merge partner halves (half 0 first -> ties prefer smaller column)
        float pdv[8]; int piv[8];
#pragma unroll
        for (int k = 0; k < 8; ++k) {
            pdv[k] = __shfl_xor_sync(0xffffffffu, kd[k], 1);
            piv[k] = __shfl_xor_sync(0xffffffffu, ki[k], 1);
        }
        if (half == 0) {
#pragma unroll
            for (int k = 0; k < 8; ++k) ins8(kd, ki, pdv[k], piv[k]);
            size_t base = (size_t)(rbase + m0 + row) * 32 + blockIdx.x * 8;
#pragma unroll
            for (int k = 0; k < 8; ++k) {
                outF[base + k] = kd[k];
                candI[base + k] = n0 + ki[k];
            }
        }
    } else if constexpr (EPI == 1) {
#pragma unroll
        for (int mt = 0; mt < 4; ++mt) {
            int nodeA = (m0 + warpM * 64 + mt * 16) >> 3;
#pragma unroll
            for (int nt8 = 0; nt8 < 4; ++nt8) {
                float c0 = acc[mt][nt8][0], c1 = acc[mt][nt8][1];
                float c2 = acc[mt][nt8][2], c3 = acc[mt][nt8][3];
#pragma unroll
                for (int m = 4; m <= 16; m <<= 1) {
                    c0 = fmaxf(c0, __shfl_xor_sync(0xffffffffu, c0, m));
                    c1 = fmaxf(c1, __shfl_xor_sync(0xffffffffu, c1, m));
                    c2 = fmaxf(c2, __shfl_xor_sync(0xffffffffu, c2, m));
                    c3 = fmaxf(c3, __shfl_xor_sync(0xffffffffu, c3, m));
                }
                if (lane < 4) {
                    int n = n0 + warpN * 32 + nt8 * 8 + lane * 2;
                    float b0 = bias[n], b1 = bias[n + 1];
                    wpair(outH, outL, (size_t)nodeA * ldOut + n,
                          lrelu(c0 + b0), lrelu(c1 + b1));
                    wpair(outH, outL, (size_t)(nodeA + 1) * ldOut + n,
                          lrelu(c2 + b0), lrelu(c3 + b1));
                }
            }
        }
    } else {
#pragma unroll
        for (int mt = 0; mt < 4; ++mt) {
            int rA = m0 + warpM * 64 + mt * 16 + (lane >> 2);
#pragma unroll
            for (int nt8 = 0; nt8 < 4; ++nt8) {
                int n = n0 + warpN * 32 + nt8 * 8 + (lane & 3) * 2;
                if (n >= Ntot) continue;
                float a0 = acc[mt][nt8][0], a1 = acc[mt][nt8][1];
                float a2 = acc[mt][nt8][2], a3 = acc[mt][nt8][3];
                float b0 = bias[n], b1 = bias[n + 1];
                float v0 = a0 + b0, v1 = a1 + b1, v2 = a2 + b0, v3 = a3 + b1;
                if (ACT) { v0 = lrelu(v0); v1 = lrelu(v1); v2 = lrelu(v2); v3 = lrelu(v3); }
                if constexpr (EPI == 0) {
                    *reinterpret_cast<float2*>(outF + (size_t)rA * ldOut + n) =
                        make_float2(v0, v1);
                    *reinterpret_cast<float2*>(outF + (size_t)(rA + 8) * ldOut + n) =
                        make_float2(v2, v3);
                } else {
                    int cm = n;
                    if constexpr (EPI == 3) { if (n >= 336) cm = n + 48; }
                    wpair(outH, outL, (size_t)rA * ldOut + cm, v0, v1);
                    wpair(outH, outL, (size_t)(rA + 8) * ldOut + cm, v2, v3);
                }
            }
        }
    }
}

// ---------------- knn merge: 4 slices x 8 candidates -> top-8 ----------------
__global__ void knnmerge_kernel(const float* __restrict__ cd, const int* __restrict__ ci,
                                int* __restrict__ knn) {
    int r = blockIdx.x * 256 + threadIdx.x;
    if (r >= BN_) return;
    float kd[8]; int ki[8];
#pragma unroll
    for (int k = 0; k < 8; ++k) { kd[k] = FLT_MAX; ki[k] = -1; }
    const float* pd = cd + (size_t)r * 32;
    const int* pi = ci + (size_t)r * 32;
#pragma unroll 4
    for (int s = 0; s < 32; ++s) ins8(kd, ki, pd[s], pi[s]);
    int b = r >> 9;
#pragma unroll
    for (int k = 0; k < 8; ++k) knn[r * 8 + k] = b * 512 + ki[k];
}

// ---------------- split / prep kernels ----------------
__global__ void splitx_kernel(const float* __restrict__ x, __nv_bfloat16* __restrict__ xh,
                              __nv_bfloat16* __restrict__ xl) {
    int idx = blockIdx.x * blockDim.x + threadIdx.x;
    if (idx >= BN_ * 64) return;
    int i = idx >> 6, f = idx & 63;
    float v = (f < 6) ? x[i * 6 + f] : 0.f;
    __nv_bfloat16 h = __float2bfloat16(v);
    xh[idx] = h;
    xl[idx] = __float2bfloat16(v - __bfloat162float(h));
}

__global__ void splitw_kernel(const float* __restrict__ W, __nv_bfloat16* __restrict__ bh,
                              __nv_bfloat16* __restrict__ bl, int K, int N, int Kpad) {
    int idx = blockIdx.x * blockDim.x + threadIdx.x;
    if (idx >= N * Kpad) return;
    int n = idx / Kpad, k = idx % Kpad;
    float v = (k < K) ? W[(size_t)k * N + n] : 0.f;
    __nv_bfloat16 h = __float2bfloat16(v);
    bh[idx] = h;
    bl[idx] = __float2bfloat16(v - __bfloat162float(h));
}

__global__ void splitw1_kernel(const float* __restrict__ w1, const float* __restrict__ b1,
                               __nv_bfloat16* __restrict__ bh, __nv_bfloat16* __restrict__ bl,
                               float* __restrict__ bcomb, int F, int Kpad) {
    int idx = blockIdx.x * blockDim.x + threadIdx.x;
    if (idx < 672) bcomb[idx] = (idx < H_) ? b1[idx] : 0.f;
    if (idx >= 672 * Kpad) return;
    int n = idx / Kpad, f = idx % Kpad;
    float v = 0.f;
    if (f < F)
        v = (n < H_) ? (w1[f * H_ + n] - w1[(F + f) * H_ + n])
                     : w1[(F + f) * H_ + (n - H_)];
    __nv_bfloat16 h = __float2bfloat16(v);
    bh[idx] = h;
    bl[idx] = __float2bfloat16(v - __bfloat162float(h));
}

__global__ void concat_kernel(const float* __restrict__ x,
                              const __nv_bfloat16* __restrict__ xoh,
                              const __nv_bfloat16* __restrict__ xol,
                              __nv_bfloat16* __restrict__ ch,
                              __nv_bfloat16* __restrict__ cl) {
    int idx = blockIdx.x * blockDim.x + threadIdx.x;
    if (idx >= BN_ * 1088) return;
    int i = idx / 1088, f = idx % 1088;
    if (f < 6) {
        float v = x[i * 6 + f];
        __nv_bfloat16 h = __float2bfloat16(v);
        ch[idx] = h;
        cl[idx] = __float2bfloat16(v - __bfloat162float(h));
    } else if (f < 1030) {
        int g = f - 6;
        int l = g >> 8, c = g & 255;
        size_t so = (size_t)l * BN_ * 256 + (size_t)i * 256 + c;
        ch[idx] = xoh[so];
        cl[idx] = xol[so];
    } else {
        ch[idx] = __float2bfloat16(0.f);
        cl[idx] = __float2bfloat16(0.f);
    }
}

__global__ void zfill_t(__nv_bfloat16* __restrict__ th, __nv_bfloat16* __restrict__ tl) {
    int idx = blockIdx.x * blockDim.x + threadIdx.x;
    if (idx >= BN_ * 48) return;
    int i = idx / 48, p = idx % 48;
    th[(size_t)i * 384 + 336 + p] = __float2bfloat16(0.f);
    tl[(size_t)i * 384 + 336 + p] = __float2bfloat16(0.f);
}

// ---------------- small kernels ----------------
__global__ void norm_kernel(const __nv_bfloat16* __restrict__ xh,
                            const __nv_bfloat16* __restrict__ xl,
                            float* __restrict__ nrm, int F) {
    int i = blockIdx.x * blockDim.x + threadIdx.x;
    if (i >= BN_) return;
    float s = 0.f;
    for (int f = 0; f < F; ++f) {
        float v = __bfloat162float(xh[(size_t)i * F + f]) +
                  __bfloat162float(xl[(size_t)i * F + f]);
        s += v * v;
    }
    nrm[i] = s;
}

__global__ void pool_kernel(const float* __restrict__ m, float* __restrict__ g) {
    int b = blockIdx.x, c = threadIdx.x;
    float s = 0.f;
    for (int n = 0; n < N_; ++n) s += m[(size_t)(b * N_ + n) * C_ + c];
    g[b * C_ + c] = s * (1.f / (float)N_);
}

__global__ void head_kernel(const float* __restrict__ g, const float* __restrict__ w1,
                            const float* __restrict__ b1, const float* __restrict__ w2,
                            const float* __restrict__ b2, float* __restrict__ out) {
    __shared__ float sg[256];
    __shared__ float sh[128];
    int b = blockIdx.x, t = threadIdx.x;
    sg[t] = g[b * 256 + t];
    sg[t + 128] = g[b * 256 + 128 + t];
    __syncthreads();
    float s = b1[t];
    for (int f = 0; f < 256; ++f) s += sg[f] * w1[f * 128 + t];
    sh[t] = lrelu(s);
    __syncthreads();
    if (t < 3) {
        float o = b2[t];
        for (int c = 0; c < 128; ++c) o += sh[c] * w2[c * 3 + t];
        out[b * 3 + t] = o;
    }
}

// ---------------- host ----------------
extern "C" void kernel_launch(void* const* d_in, const int* in_sizes, int n_in,
                              void* d_out, int out_size) {
    const float* x = (const float*)d_in[0];
    const float *cw1[4], *cb1[4], *cw2[4], *cb2[4];
    for (int L = 0; L < 4; ++L) {
        cw1[L] = (const float*)d_in[3 + 4 * L];
        cb1[L] = (const float*)d_in[4 + 4 * L];
        cw2[L] = (const float*)d_in[5 + 4 * L];
        cb2[L] = (const float*)d_in[6 + 4 * L];
    }
    const float* m1w1 = (const float*)d_in[19];
    const float* m1b1 = (const float*)d_in[20];
    const float* m1w2 = (const float*)d_in[21];
    const float* m1b2 = (const float*)d_in[22];
    const float* m2w1 = (const float*)d_in[23];
    const float* m2b1 = (const float*)d_in[24];
    const float* m2w2 = (const float*)d_in[25];
    const float* m2b2 = (const float*)d_in[26];
    float* out = (float*)d_out;

    float *p_nrm, *p_m, *p_pool, *p_bc, *p_cd;
    int *p_knn, *p_ci;
    __nv_bfloat16 *p_xsh, *p_xsl, *p_xoh, *p_xol, *p_abh, *p_abl;
    __nv_bfloat16 *p_cath, *p_catl, *p_th, *p_tl, *p_bh1, *p_bl1, *p_bh2, *p_bl2;
    cudaGetSymbolAddress((void**)&p_knn, g_knn);
    cudaGetSymbolAddress((void**)&p_nrm, g_norm);
    cudaGetSymbolAddress((void**)&p_m, g_m);
    cudaGetSymbolAddress((void**)&p_pool, g_pool);
    cudaGetSymbolAddress((void**)&p_bc, g_bcomb);
    cudaGetSymbolAddress((void**)&p_cd, g_candd);
    cudaGetSymbolAddress((void**)&p_ci, g_candi);
    cudaGetSymbolAddress((void**)&p_xsh, g_xsh);
    cudaGetSymbolAddress((void**)&p_xsl, g_xsl);
    cudaGetSymbolAddress((void**)&p_xoh, g_xoh);
    cudaGetSymbolAddress((void**)&p_xol, g_xol);
    cudaGetSymbolAddress((void**)&p_abh, g_abh);
    cudaGetSymbolAddress((void**)&p_abl, g_abl);
    cudaGetSymbolAddress((void**)&p_cath, g_cath);
    cudaGetSymbolAddress((void**)&p_catl, g_catl);
    cudaGetSymbolAddress((void**)&p_th, g_th);
    cudaGetSymbolAddress((void**)&p_tl, g_tl);
    cudaGetSymbolAddress((void**)&p_bh1, g_bh1);
    cudaGetSymbolAddress((void**)&p_bl1, g_bl1);
    cudaGetSymbolAddress((void**)&p_bh2, g_bh2);
    cudaGetSymbolAddress((void**)&p_bl2, g_bl2);

    cudaFuncSetAttribute(tc_gemm<0, 2, 0>, cudaFuncAttributeMaxDynamicSharedMemorySize, SMEM_SZ);
    cudaFuncSetAttribute(tc_gemm<0, 3, 0>, cudaFuncAttributeMaxDynamicSharedMemorySize, SMEM_SZ);
    cudaFuncSetAttribute(tc_gemm<1, 1, 0>, cudaFuncAttributeMaxDynamicSharedMemorySize, SMEM_SZ);
    cudaFuncSetAttribute(tc_gemm<0, 4, 1>, cudaFuncAttributeMaxDynamicSharedMemorySize, SMEM_SZ);
    cudaFuncSetAttribute(tc_gemm<0, 0, 1>, cudaFuncAttributeMaxDynamicSharedMemorySize, SMEM_SZ);

    splitx_kernel<<<(BN_ * 64 + 255) / 256, 256>>>(x, p_xsh, p_xsl);
    zfill_t<<<(BN_ * 48 + 255) / 256, 256>>>(p_th, p_tl);

    for (int L = 0; L < 4; ++L) {
        const __nv_bfloat16* xh = L ? p_xoh + (size_t)(L - 1) * BN_ * 256 : p_xsh;
        const __nv_bfloat16* xl = L ? p_xol + (size_t)(L - 1) * BN_ * 256 : p_xsl;
        int aK = L ? 256 : 64;
        int F = L ? 256 : 6;

        norm_kernel<<<BN_ / 256, 256>>>(xh, xl, p_nrm, aK);
        // distance GEMM with fused per-slice top-8
        tc_gemm<0, 2, 0><<<dim3(4, 4, B_), 256, SMEM_SZ>>>(
            xh, xl, aK, nullptr, xh, xl, aK, nullptr, p_nrm,
            p_cd, nullptr, nullptr, p_ci, N_, N_, aK / 32, N_);
        knnmerge_kernel<<<BN_ / 256, 256>>>(p_cd, p_ci, p_knn);
        splitw1_kernel<<<(672 * aK + 255) / 256, 256>>>(cw1[L], cb1[L], p_bh1, p_bl1,
                                                        p_bc, F, aK);
        tc_gemm<0, 3, 0><<<dim3(6, BN_ / 128), 256, SMEM_SZ>>>(
            xh, xl, aK, nullptr, p_bh1, p_bl1, aK, p_bc, nullptr,
            nullptr, p_abh, p_abl, nullptr, 768, 672, aK / 32, 0);
        splitw_kernel<<<(256 * 384 + 255) / 256, 256>>>(cw2[L], p_bh2, p_bl2, H_, C_, 384);
        tc_gemm<1, 1, 0><<<dim3(2, (BN_ * K_) / 128), 256, SMEM_SZ>>>(
            p_abh, p_abl, 768, p_knn, p_bh2, p_bl2, 384, cb2[L], nullptr,
            nullptr, p_xoh + (size_t)L * BN_ * 256, p_xol + (size_t)L * BN_ * 256,
            nullptr, 256, 256, 12, 0);
    }

    concat_kernel<<<(BN_ * 1088 + 255) / 256, 256>>>(x, p_xoh, p_xol, p_cath, p_catl);
    splitw_kernel<<<(336 * 1088 + 255) / 256, 256>>>(m1w1, p_bh1, p_bl1, 1030, H_, 1088);
    tc_gemm<0, 4, 1><<<dim3(3, BN_ / 128), 256, SMEM_SZ>>>(
        p_cath, p_catl, 1088, nullptr, p_bh1, p_bl1, 1088, m1b1, nullptr,
        nullptr, p_th, p_tl, nullptr, 384, H_, 34, 0);
    splitw_kernel<<<(256 * 384 + 255) / 256, 256>>>(m1w2, p_bh2, p_bl2, H_, C_, 384);
    tc_gemm<0, 0, 1><<<dim3(2, BN_ / 128), 256, SMEM_SZ>>>(
        p_th, p_tl, 384, nullptr, p_bh2, p_bl2, 384, m1b2, nullptr,
        p_m, nullptr, nullptr, nullptr, 256, 256, 12, 0);
    pool_kernel<<<B_, 256>>>(p_m, p_pool);
    head_kernel<<<B_, 128>>>(p_pool, m2w1, m2b1, m2w2, m2b2, out);
}